// round 13
// baseline (speedup 1.0000x reference)
#include <cuda_runtime.h>
#include <cuda_fp16.h>
#include <cstdint>

// ============================================================
// Problem dims
// ============================================================
#define B_DIM 4096
#define IN_DIM 1024
#define H_DIM 1024
#define KK 2048            // IN + H (K of the GEMM)
#define NT 5120            // 5*H  (reordered: per-h tuple [i,f,o,c0,c1])

// GEMM tiling
#define BM 128
#define BN 80              // 16 h-tuples of 5 columns
#define BK 32
#define NCHUNK (KK / BK)   // 64
#define STAGES 4
#define THREADS 256

// smem: fp16 tiles with 40-element (80B) row pitch (conflict-free for LDSM)
#define PITCH_B 80
#define A_TILE_B (BM * PITCH_B)          // 10240
#define B_TILE_B (BN * PITCH_B)          // 6400
#define OFF_A 0
#define OFF_B A_TILE_B
#define STAGE_B (A_TILE_B + B_TILE_B)    // 16640
#define EPI_PITCH 84                     // floats, padded (80 cols)
#define SMEM_TOTAL (STAGES * STAGE_B)    // 66560 (>= epilogue 128*84*4 = 43008)

// ============================================================
// Scratch (__device__ globals: allocation-free rule)
// ============================================================
__device__ __half g_A[(size_t)B_DIM * KK];
__device__ __half g_W[(size_t)NT * KK];   // row n' = 5*h + j, j in {i,f,o,c0,c1}

// ============================================================
// PTX helpers (baseline-family ISA only: no 'a'-suffix features)
// ============================================================
__device__ __forceinline__ uint32_t smem_u32(const void* p) {
    uint32_t a;
    asm("{ .reg .u64 t; cvta.to.shared.u64 t, %1; cvt.u32.u64 %0, t; }"
        : "=r"(a) : "l"(p));
    return a;
}

__device__ __forceinline__ void cp_async16(uint32_t s, const void* g) {
    asm volatile("cp.async.cg.shared.global [%0], [%1], 16;" :: "r"(s), "l"(g));
}
#define CP_COMMIT() asm volatile("cp.async.commit_group;" ::: "memory")
#define CP_WAIT2()  asm volatile("cp.async.wait_group 2;" ::: "memory")
#define CP_WAIT0()  asm volatile("cp.async.wait_group 0;" ::: "memory")

__device__ __forceinline__ void ldsm_x4(uint32_t* r, uint32_t addr) {
    asm volatile("ldmatrix.sync.aligned.m8n8.x4.shared.b16 {%0,%1,%2,%3}, [%4];"
                 : "=r"(r[0]), "=r"(r[1]), "=r"(r[2]), "=r"(r[3]) : "r"(addr));
}
__device__ __forceinline__ void ldsm_x2(uint32_t* r, uint32_t addr) {
    asm volatile("ldmatrix.sync.aligned.m8n8.x2.shared.b16 {%0,%1}, [%2];"
                 : "=r"(r[0]), "=r"(r[1]) : "r"(addr));
}

// f16-accumulator HMMA (the double-rate experiment): D(f16) += A*B
__device__ __forceinline__ void mma_f16acc(uint32_t* c, const uint32_t* a, const uint32_t* b) {
    asm volatile(
        "mma.sync.aligned.m16n8k16.row.col.f16.f16.f16.f16 "
        "{%0,%1}, {%2,%3,%4,%5}, {%6,%7}, {%0,%1};"
        : "+r"(c[0]), "+r"(c[1])
        : "r"(a[0]), "r"(a[1]), "r"(a[2]), "r"(a[3]), "r"(b[0]), "r"(b[1]));
}

// round float4 -> 4 fp16 packed in uint2
__device__ __forceinline__ uint2 round4h(float4 v) {
    __half2 a = __halves2half2(__float2half(v.x), __float2half(v.y));
    __half2 b = __halves2half2(__float2half(v.z), __float2half(v.w));
    uint2 o;
    o.x = *(uint32_t*)&a; o.y = *(uint32_t*)&b;
    return o;
}

// ============================================================
// Kernel 1a: round combined [x | h_prev] to fp16, K-major
// ============================================================
__global__ __launch_bounds__(256)
void convA_kernel(const float* __restrict__ x, const float* __restrict__ h) {
    size_t i = (size_t)blockIdx.x * 256 + threadIdx.x;      // over B*KK/4
    if (i >= (size_t)B_DIM * KK / 4) return;
    size_t b  = i / (KK / 4);
    int    k4 = (int)(i % (KK / 4)) * 4;
    float4 v = (k4 < IN_DIM)
             ? *(const float4*)(x + b * IN_DIM + k4)
             : *(const float4*)(h + b * H_DIM + (k4 - IN_DIM));
    *(uint2*)(g_A + b * KK + k4) = round4h(v);
}

// Kernel 1b: fp16-round + REORDER W.  Row n' = 5*h + j:
//   j=0,1,2 -> Wg[j*1024 + h],  j=3,4 -> Wc[2*h + (j-3)]
__global__ __launch_bounds__(256)
void convW_kernel(const float* __restrict__ Wg, const float* __restrict__ Wc) {
    size_t i = (size_t)blockIdx.x * 256 + threadIdx.x;      // over NT*KK/4
    if (i >= (size_t)NT * KK / 4) return;
    size_t np = i / (KK / 4);
    int    k4 = (int)(i % (KK / 4)) * 4;
    int    hh = (int)(np / 5);
    int    j  = (int)(np % 5);
    const float* src = (j < 3) ? (Wg + ((size_t)j * H_DIM + hh) * KK + k4)
                               : (Wc + ((size_t)2 * hh + (j - 3)) * KK + k4);
    *(uint2*)(g_W + np * KK + k4) = round4h(*(const float4*)src);
}

// ============================================================
// Kernel 2: fused GEMM (HMMA f16-acc, chunk-promoted to f32) + LSTM epilogue
//   2 CTAs/SM: BM=128 x BN=80, 8 warps (4 M x 2 N), warp tile 32x40
// ============================================================
__global__ __launch_bounds__(THREADS, 2)
void gemm_fused_kernel(const float* __restrict__ c_prev,
                       const float* __restrict__ bg, const float* __restrict__ bc,
                       const float* __restrict__ W1, const float* __restrict__ b1,
                       const float* __restrict__ W2, const float* __restrict__ b2,
                       float* __restrict__ out) {
    extern __shared__ __align__(128) char smem[];
    __shared__ float4 wk[32];     // {W1[k,0], W1[k,1], b1[k], W2[k]}
    __shared__ float  s_b2;

    const uint32_t sb = smem_u32(smem);
    const int tid  = threadIdx.x;
    const int wid  = tid >> 5;
    const int lane = tid & 31;
    const int wm   = wid >> 1;          // 0..3  (M warps, 32 rows each)
    const int wn   = wid & 1;           // 0..1  (N warps, 40 cols each)
    const int m0   = blockIdx.y * BM;
    const int hb0  = blockIdx.x * 16;   // first h of this CTA (16 tuples)
    const int n0   = hb0 * 5;           // first W' row

    if (tid < 32) wk[tid] = make_float4(W1[2 * tid], W1[2 * tid + 1], b1[tid], W2[tid]);
    if (tid == 0) s_b2 = b2[0];

    // ---- cp.async source/dest offsets (per thread) ----
    // A: 512 vec16 per tile (128 rows x 4); B: 320 (80 x 4).
    // smem row pitch 80B -> rows 0..7 mod 128B = {0,80,32,112,64,16,96,48}: LDSM conflict-free.
    uint32_t sA[2]; size_t gA[2];
#pragma unroll
    for (int j = 0; j < 2; ++j) {
        int v = tid + j * 256;                  // 0..511
        int r = v >> 2, c = v & 3;
        sA[j] = (uint32_t)(r * PITCH_B + c * 16);
        gA[j] = (size_t)(m0 + r) * KK + c * 8;
    }
    uint32_t sB[2]; size_t gB[2];
#pragma unroll
    for (int j = 0; j < 2; ++j) {
        int v = tid + j * 256;                  // 0..511 (guard < 320)
        int r = v >> 2, c = v & 3;
        sB[j] = (uint32_t)(r * PITCH_B + c * 16);
        gB[j] = (size_t)(n0 + r) * KK + c * 8;
    }
    const bool bok = (tid < 64);                // j==1 guard (256+tid < 320)

    // ---- LDSM base addresses ----
    const uint32_t aoff = (uint32_t)((wm * 32 + (lane & 15)) * PITCH_B + (lane >> 4) * 16);
    const uint32_t boff = (uint32_t)((wn * 40 + (lane & 7)) * PITCH_B + ((lane >> 3) & 1) * 16);

    float acc[2][5][4];
#pragma unroll
    for (int mi = 0; mi < 2; ++mi)
#pragma unroll
        for (int ni = 0; ni < 5; ++ni)
#pragma unroll
            for (int q = 0; q < 4; ++q) acc[mi][ni][q] = 0.f;

    // ---- pipeline prologue: stages 0..2 ----
#pragma unroll
    for (int pc = 0; pc < 3; ++pc) {
        const uint32_t st = sb + pc * STAGE_B;
        const int k0 = pc * BK;
#pragma unroll
        for (int j = 0; j < 2; ++j)
            cp_async16(st + OFF_A + sA[j], g_A + gA[j] + k0);
        cp_async16(st + OFF_B + sB[0], g_W + gB[0] + k0);
        if (bok) cp_async16(st + OFF_B + sB[1], g_W + gB[1] + k0);
        CP_COMMIT();
    }

    // ---- main loop ----
    for (int kc = 0; kc < NCHUNK; ++kc) {
        CP_WAIT2();          // stage kc resident (<=2 newer groups pending)
        __syncthreads();

        // issue stage kc+3 (its buffer was consumed in iter kc-1; all warps passed the sync)
        {
            const int kn = kc + 3;
            if (kn < NCHUNK) {
                const uint32_t st = sb + (kn % STAGES) * STAGE_B;
                const int k0 = kn * BK;
#pragma unroll
                for (int j = 0; j < 2; ++j)
                    cp_async16(st + OFF_A + sA[j], g_A + gA[j] + k0);
                cp_async16(st + OFF_B + sB[0], g_W + gB[0] + k0);
                if (bok) cp_async16(st + OFF_B + sB[1], g_W + gB[1] + k0);
            }
            CP_COMMIT();   // commit (possibly empty) to keep group accounting uniform
        }

        const uint32_t st = sb + (kc % STAGES) * STAGE_B;

        // f16 chunk accumulators (fresh per BK=32 chunk: 2 chained k16 MMAs)
        uint32_t c16[2][5][2];
#pragma unroll
        for (int mi = 0; mi < 2; ++mi)
#pragma unroll
            for (int ni = 0; ni < 5; ++ni) {
                c16[mi][ni][0] = 0u; c16[mi][ni][1] = 0u;
            }

#pragma unroll
        for (int s = 0; s < 2; ++s) {           // two k16 steps per BK=32
            uint32_t av[2][4], bv[5][2];
#pragma unroll
            for (int mi = 0; mi < 2; ++mi)
                ldsm_x4(av[mi], st + OFF_A + aoff + mi * 16 * PITCH_B + s * 32);
#pragma unroll
            for (int ni = 0; ni < 5; ++ni)
                ldsm_x2(bv[ni], st + OFF_B + boff + ni * 8 * PITCH_B + s * 32);
#pragma unroll
            for (int mi = 0; mi < 2; ++mi)
#pragma unroll
                for (int ni = 0; ni < 5; ++ni)
                    mma_f16acc(c16[mi][ni], av[mi], bv[ni]);
        }

        // promote chunk result into fp32 master accumulators (FMA pipe,
        // overlaps the tensor pipe of neighbouring warps)
#pragma unroll
        for (int mi = 0; mi < 2; ++mi)
#pragma unroll
            for (int ni = 0; ni < 5; ++ni) {
                float2 f0 = __half22float2(*(__half2*)&c16[mi][ni][0]);
                float2 f1 = __half22float2(*(__half2*)&c16[mi][ni][1]);
                acc[mi][ni][0] += f0.x;
                acc[mi][ni][1] += f0.y;
                acc[mi][ni][2] += f1.x;
                acc[mi][ni][3] += f1.y;
            }
    }
    CP_WAIT0();
    __syncthreads();    // done with stage buffers -> reuse smem for epilogue

    // ---- spill accumulators to smem [128][80] (pitch 84 floats) ----
    float* sf = (float*)smem;
    {
        const int r0 = wm * 32 + (lane >> 2);
        const int c0 = wn * 40 + (lane & 3) * 2;
#pragma unroll
        for (int mi = 0; mi < 2; ++mi)
#pragma unroll
            for (int ni = 0; ni < 5; ++ni) {
                const int rr = r0 + mi * 16;
                const int cc = c0 + ni * 8;
                sf[rr * EPI_PITCH + cc]            = acc[mi][ni][0];
                sf[rr * EPI_PITCH + cc + 1]        = acc[mi][ni][1];
                sf[(rr + 8) * EPI_PITCH + cc]      = acc[mi][ni][2];
                sf[(rr + 8) * EPI_PITCH + cc + 1]  = acc[mi][ni][3];
            }
    }
    __syncthreads();

    // ---- fused LSTM epilogue: 128 rows x 16 h per CTA ----
    for (int i = tid; i < BM * 16; i += THREADS) {
        const int r  = i >> 4;          // local m row
        const int hl = i & 15;          // local h
        const int b  = m0 + r;
        const int h  = hb0 + hl;
        const float* row = sf + r * EPI_PITCH + hl * 5;

        float iv = 1.f / (1.f + __expf(-(row[0] + bg[h])));
        float fv = 1.f / (1.f + __expf(-(row[1] + bg[H_DIM + h])));
        float ov = 1.f / (1.f + __expf(-(row[2] + bg[2 * H_DIM + h])));
        float p0 = row[3] + bc[2 * h];
        float p1 = row[4] + bc[2 * h + 1];

        float gsum = s_b2;
#pragma unroll
        for (int k = 0; k < 32; ++k) {
            float4 w = wk[k];
            float hid = fmaxf(w.x * p0 + w.y * p1 + w.z, 0.f);
            gsum += w.w * hid;
        }

        float c = fv * c_prev[(size_t)b * H_DIM + h] + iv * gsum;
        out[(size_t)b * H_DIM + h] = ov * tanhf(c);
        out[(size_t)B_DIM * H_DIM + (size_t)b * H_DIM + h] = c;
    }
}

// ============================================================
// Launch
// ============================================================
extern "C" void kernel_launch(void* const* d_in, const int* in_sizes, int n_in,
                              void* d_out, int out_size) {
    const float* x      = (const float*)d_in[0];
    const float* h_prev = (const float*)d_in[1];
    const float* c_prev = (const float*)d_in[2];
    const float* Wg     = (const float*)d_in[3];
    const float* bg     = (const float*)d_in[4];
    const float* Wc     = (const float*)d_in[5];
    const float* bc     = (const float*)d_in[6];
    const float* W1     = (const float*)d_in[7];
    const float* b1     = (const float*)d_in[8];
    const float* W2     = (const float*)d_in[9];
    const float* b2     = (const float*)d_in[10];
    float* out = (float*)d_out;

    convA_kernel<<<(int)(((size_t)B_DIM * KK / 4 + 255) / 256), 256>>>(x, h_prev);
    convW_kernel<<<(int)(((size_t)NT * KK / 4 + 255) / 256), 256>>>(Wg, Wc);

    cudaFuncSetAttribute(gemm_fused_kernel,
                         cudaFuncAttributeMaxDynamicSharedMemorySize, SMEM_TOTAL);
    dim3 grid(H_DIM / 16, B_DIM / BM);   // 64 x 32 = 2048 CTAs
    gemm_fused_kernel<<<grid, THREADS, SMEM_TOTAL>>>(c_prev, bg, bc, W1, b1, W2, b2, out);
}

// round 14
// speedup vs baseline: 1.1474x; 1.1474x over previous
#include <cuda_runtime.h>
#include <cuda_fp16.h>
#include <cstdint>

// ============================================================
// Problem dims
// ============================================================
#define B_DIM 4096
#define IN_DIM 1024
#define H_DIM 1024
#define KK 2048            // IN + H (K of the GEMM)
#define NT 5120            // 5*H  (reordered: per-h tuple [i,f,o,c0,c1])

// GEMM tiling
#define BM 128
#define BN 80              // 16 h-tuples of 5 columns
#define BK 64
#define NCHUNK (KK / BK)   // 32
#define STAGES 3
#define THREADS 256

// smem: fp16 tiles with 72-element (144B) row pitch.
// 144 = 16*9, 9 coprime to 8 -> 8 consecutive rows hit 8 distinct 16B bank
// groups (offsets mod 128 = 0,16,32,...,112): LDSM conflict-free.
#define PITCH_B 144
#define A_TILE_B (BM * PITCH_B)          // 18432
#define B_TILE_B (BN * PITCH_B)          // 11520
#define OFF_A 0
#define OFF_B A_TILE_B
#define STAGE_B (A_TILE_B + B_TILE_B)    // 29952
#define EPI_PITCH 84                     // floats, padded (80 cols)
#define SMEM_TOTAL (STAGES * STAGE_B)    // 89856 (>= epilogue 128*84*4 = 43008)

// ============================================================
// Scratch (__device__ globals: allocation-free rule)
// ============================================================
__device__ __half g_A[(size_t)B_DIM * KK];
__device__ __half g_W[(size_t)NT * KK];   // row n' = 5*h + j, j in {i,f,o,c0,c1}

// ============================================================
// PTX helpers (baseline-family ISA only: no 'a'-suffix features)
// ============================================================
__device__ __forceinline__ uint32_t smem_u32(const void* p) {
    uint32_t a;
    asm("{ .reg .u64 t; cvta.to.shared.u64 t, %1; cvt.u32.u64 %0, t; }"
        : "=r"(a) : "l"(p));
    return a;
}

__device__ __forceinline__ void cp_async16(uint32_t s, const void* g) {
    asm volatile("cp.async.cg.shared.global [%0], [%1], 16;" :: "r"(s), "l"(g));
}
#define CP_COMMIT() asm volatile("cp.async.commit_group;" ::: "memory")
#define CP_WAIT1()  asm volatile("cp.async.wait_group 1;" ::: "memory")
#define CP_WAIT0()  asm volatile("cp.async.wait_group 0;" ::: "memory")

__device__ __forceinline__ void ldsm_x4(uint32_t* r, uint32_t addr) {
    asm volatile("ldmatrix.sync.aligned.m8n8.x4.shared.b16 {%0,%1,%2,%3}, [%4];"
                 : "=r"(r[0]), "=r"(r[1]), "=r"(r[2]), "=r"(r[3]) : "r"(addr));
}
__device__ __forceinline__ void ldsm_x2(uint32_t* r, uint32_t addr) {
    asm volatile("ldmatrix.sync.aligned.m8n8.x2.shared.b16 {%0,%1}, [%2];"
                 : "=r"(r[0]), "=r"(r[1]) : "r"(addr));
}
__device__ __forceinline__ void mma_fp16(float* c, const uint32_t* a, const uint32_t* b) {
    asm volatile(
        "mma.sync.aligned.m16n8k16.row.col.f32.f16.f16.f32 "
        "{%0,%1,%2,%3}, {%4,%5,%6,%7}, {%8,%9}, {%0,%1,%2,%3};"
        : "+f"(c[0]), "+f"(c[1]), "+f"(c[2]), "+f"(c[3])
        : "r"(a[0]), "r"(a[1]), "r"(a[2]), "r"(a[3]), "r"(b[0]), "r"(b[1]));
}

// round float4 -> 4 fp16 packed in uint2
__device__ __forceinline__ uint2 round4h(float4 v) {
    __half2 a = __halves2half2(__float2half(v.x), __float2half(v.y));
    __half2 b = __halves2half2(__float2half(v.z), __float2half(v.w));
    uint2 o;
    o.x = *(uint32_t*)&a; o.y = *(uint32_t*)&b;
    return o;
}

// ============================================================
// Kernel 1 (merged): fp16-round A (= [x|h_prev]) and reordered W
//   blocks [0, A_BLOCKS)           -> A elements
//   blocks [A_BLOCKS, TOTAL_BLOCKS)-> W elements
//   W row n' = 5*h + j: j=0,1,2 -> Wg[j*1024 + h], j=3,4 -> Wc[2*h + (j-3)]
// ============================================================
#define A_ITEMS ((size_t)B_DIM * KK / 4)     // 2097152
#define W_ITEMS ((size_t)NT * KK / 4)        // 2621440
#define A_BLOCKS ((int)(A_ITEMS / 256))      // 8192
#define W_BLOCKS ((int)(W_ITEMS / 256))      // 10240

__global__ __launch_bounds__(256)
void conv_kernel(const float* __restrict__ x, const float* __restrict__ h,
                 const float* __restrict__ Wg, const float* __restrict__ Wc) {
    if (blockIdx.x < A_BLOCKS) {
        size_t i = (size_t)blockIdx.x * 256 + threadIdx.x;
        size_t b  = i / (KK / 4);
        int    k4 = (int)(i % (KK / 4)) * 4;
        float4 v = (k4 < IN_DIM)
                 ? *(const float4*)(x + b * IN_DIM + k4)
                 : *(const float4*)(h + b * H_DIM + (k4 - IN_DIM));
        *(uint2*)(g_A + b * KK + k4) = round4h(v);
    } else {
        size_t i = (size_t)(blockIdx.x - A_BLOCKS) * 256 + threadIdx.x;
        size_t np = i / (KK / 4);
        int    k4 = (int)(i % (KK / 4)) * 4;
        int    hh = (int)(np / 5);
        int    j  = (int)(np % 5);
        const float* src = (j < 3) ? (Wg + ((size_t)j * H_DIM + hh) * KK + k4)
                                   : (Wc + ((size_t)2 * hh + (j - 3)) * KK + k4);
        *(uint2*)(g_W + np * KK + k4) = round4h(*(const float4*)src);
    }
}

// ============================================================
// Kernel 2: fused GEMM (HMMA, 1-pass fp16, fp32 acc) + LSTM epilogue
//   2 CTAs/SM: BM=128 x BN=80, 8 warps (4 M x 2 N), warp tile 32x40
// ============================================================
__global__ __launch_bounds__(THREADS, 2)
void gemm_fused_kernel(const float* __restrict__ c_prev,
                       const float* __restrict__ bg, const float* __restrict__ bc,
                       const float* __restrict__ W1, const float* __restrict__ b1,
                       const float* __restrict__ W2, const float* __restrict__ b2,
                       float* __restrict__ out) {
    extern __shared__ __align__(128) char smem[];
    __shared__ float4 wk[32];     // {W1[k,0], W1[k,1], b1[k], W2[k]}
    __shared__ float  s_b2;

    const uint32_t sb = smem_u32(smem);
    const int tid  = threadIdx.x;
    const int wid  = tid >> 5;
    const int lane = tid & 31;
    const int wm   = wid >> 1;          // 0..3  (M warps, 32 rows each)
    const int wn   = wid & 1;           // 0..1  (N warps, 40 cols each)
    const int m0   = blockIdx.y * BM;
    const int hb0  = blockIdx.x * 16;   // first h of this CTA (16 tuples)
    const int n0   = hb0 * 5;           // first W' row

    if (tid < 32) wk[tid] = make_float4(W1[2 * tid], W1[2 * tid + 1], b1[tid], W2[tid]);
    if (tid == 0) s_b2 = b2[0];

    // ---- cp.async source/dest offsets (per thread) ----
    // BK=64 halves: 8 vec16 per row. A: 128 rows x 8 = 1024 vecs; B: 80 x 8 = 640.
    uint32_t sA[4]; size_t gA[4];
#pragma unroll
    for (int j = 0; j < 4; ++j) {
        int v = tid + j * 256;                  // 0..1023
        int r = v >> 3, c = v & 7;
        sA[j] = (uint32_t)(r * PITCH_B + c * 16);
        gA[j] = (size_t)(m0 + r) * KK + c * 8;
    }
    uint32_t sB[3]; size_t gB[3];
#pragma unroll
    for (int j = 0; j < 3; ++j) {
        int v = tid + j * 256;                  // 0..767 (guard < 640)
        int r = v >> 3, c = v & 7;
        sB[j] = (uint32_t)(r * PITCH_B + c * 16);
        gB[j] = (size_t)(n0 + r) * KK + c * 8;
    }
    const bool bok = (tid < 128);               // j==2 guard (512+tid < 640)

    // ---- LDSM base addresses ----
    const uint32_t aoff = (uint32_t)((wm * 32 + (lane & 15)) * PITCH_B + (lane >> 4) * 16);
    const uint32_t boff = (uint32_t)((wn * 40 + (lane & 7)) * PITCH_B + ((lane >> 3) & 1) * 16);

    float acc[2][5][4];
#pragma unroll
    for (int mi = 0; mi < 2; ++mi)
#pragma unroll
        for (int ni = 0; ni < 5; ++ni)
#pragma unroll
            for (int q = 0; q < 4; ++q) acc[mi][ni][q] = 0.f;

    // ---- pipeline prologue: stages 0,1 ----
#pragma unroll
    for (int pc = 0; pc < 2; ++pc) {
        const uint32_t st = sb + pc * STAGE_B;
        const int k0 = pc * BK;
#pragma unroll
        for (int j = 0; j < 4; ++j)
            cp_async16(st + OFF_A + sA[j], g_A + gA[j] + k0);
#pragma unroll
        for (int j = 0; j < 3; ++j)
            if (j < 2 || bok) cp_async16(st + OFF_B + sB[j], g_W + gB[j] + k0);
        CP_COMMIT();
    }

    // ---- main loop ----
    for (int kc = 0; kc < NCHUNK; ++kc) {
        CP_WAIT1();          // stage kc resident (<=1 newer group pending)
        __syncthreads();

        // issue stage kc+2 (its buffer was consumed in iter kc-1; all warps passed the sync)
        {
            const int kn = kc + 2;
            if (kn < NCHUNK) {
                const uint32_t st = sb + (kn % STAGES) * STAGE_B;
                const int k0 = kn * BK;
#pragma unroll
                for (int j = 0; j < 4; ++j)
                    cp_async16(st + OFF_A + sA[j], g_A + gA[j] + k0);
#pragma unroll
                for (int j = 0; j < 3; ++j)
                    if (j < 2 || bok) cp_async16(st + OFF_B + sB[j], g_W + gB[j] + k0);
            }
            CP_COMMIT();   // commit (possibly empty) to keep group accounting uniform
        }

        const uint32_t st = sb + (kc % STAGES) * STAGE_B;
#pragma unroll
        for (int s = 0; s < 4; ++s) {           // four k16 steps per BK=64
            uint32_t av[2][4], bv[5][2];
#pragma unroll
            for (int mi = 0; mi < 2; ++mi)
                ldsm_x4(av[mi], st + OFF_A + aoff + mi * 16 * PITCH_B + s * 32);
#pragma unroll
            for (int ni = 0; ni < 5; ++ni)
                ldsm_x2(bv[ni], st + OFF_B + boff + ni * 8 * PITCH_B + s * 32);
#pragma unroll
            for (int mi = 0; mi < 2; ++mi)
#pragma unroll
                for (int ni = 0; ni < 5; ++ni)
                    mma_fp16(acc[mi][ni], av[mi], bv[ni]);
        }
    }
    CP_WAIT0();
    __syncthreads();    // done with stage buffers -> reuse smem for epilogue

    // ---- spill accumulators to smem [128][80] (pitch 84 floats) ----
    float* sf = (float*)smem;
    {
        const int r0 = wm * 32 + (lane >> 2);
        const int c0 = wn * 40 + (lane & 3) * 2;
#pragma unroll
        for (int mi = 0; mi < 2; ++mi)
#pragma unroll
            for (int ni = 0; ni < 5; ++ni) {
                const int rr = r0 + mi * 16;
                const int cc = c0 + ni * 8;
                sf[rr * EPI_PITCH + cc]            = acc[mi][ni][0];
                sf[rr * EPI_PITCH + cc + 1]        = acc[mi][ni][1];
                sf[(rr + 8) * EPI_PITCH + cc]      = acc[mi][ni][2];
                sf[(rr + 8) * EPI_PITCH + cc + 1]  = acc[mi][ni][3];
            }
    }
    __syncthreads();

    // ---- fused LSTM epilogue: 128 rows x 16 h per CTA ----
    for (int i = tid; i < BM * 16; i += THREADS) {
        const int r  = i >> 4;          // local m row
        const int hl = i & 15;          // local h
        const int b  = m0 + r;
        const int h  = hb0 + hl;
        const float* row = sf + r * EPI_PITCH + hl * 5;

        float iv = 1.f / (1.f + __expf(-(row[0] + bg[h])));
        float fv = 1.f / (1.f + __expf(-(row[1] + bg[H_DIM + h])));
        float ov = 1.f / (1.f + __expf(-(row[2] + bg[2 * H_DIM + h])));
        float p0 = row[3] + bc[2 * h];
        float p1 = row[4] + bc[2 * h + 1];

        float gsum = s_b2;
#pragma unroll
        for (int k = 0; k < 32; ++k) {
            float4 w = wk[k];
            float hid = fmaxf(w.x * p0 + w.y * p1 + w.z, 0.f);
            gsum += w.w * hid;
        }

        float c = fv * c_prev[(size_t)b * H_DIM + h] + iv * gsum;
        out[(size_t)b * H_DIM + h] = ov * tanhf(c);
        out[(size_t)B_DIM * H_DIM + (size_t)b * H_DIM + h] = c;
    }
}

// ============================================================
// Launch
// ============================================================
extern "C" void kernel_launch(void* const* d_in, const int* in_sizes, int n_in,
                              void* d_out, int out_size) {
    const float* x      = (const float*)d_in[0];
    const float* h_prev = (const float*)d_in[1];
    const float* c_prev = (const float*)d_in[2];
    const float* Wg     = (const float*)d_in[3];
    const float* bg     = (const float*)d_in[4];
    const float* Wc     = (const float*)d_in[5];
    const float* bc     = (const float*)d_in[6];
    const float* W1     = (const float*)d_in[7];
    const float* b1     = (const float*)d_in[8];
    const float* W2     = (const float*)d_in[9];
    const float* b2     = (const float*)d_in[10];
    float* out = (float*)d_out;

    conv_kernel<<<A_BLOCKS + W_BLOCKS, 256>>>(x, h_prev, Wg, Wc);

    cudaFuncSetAttribute(gemm_fused_kernel,
                         cudaFuncAttributeMaxDynamicSharedMemorySize, SMEM_TOTAL);
    dim3 grid(H_DIM / 16, B_DIM / BM);   // 64 x 32 = 2048 CTAs
    gemm_fused_kernel<<<grid, THREADS, SMEM_TOTAL>>>(c_prev, bg, bc, W1, b1, W2, b2, out);
}